// round 16
// baseline (speedup 1.0000x reference)
#include <cuda_runtime.h>
#include <cstdint>

// LoRA linear via rank-16 factor — warp-specialized persistent fusion.
// Per CTA (1 per SM, 512 thr): warps 0-7 produce t = x_tile @ A^T (R6 pipeline),
// warps 8-15 consume t -> out_tile = t @ B^T (R6 stage2 form), overlapped
// across tiles via double-buffered smem t and named-barrier FULL/EMPTY pairs.

#define D 4096
#define R 16
#define ROWS_TOTAL 16384
#define TILE_ROWS 32
#define NT (ROWS_TOTAL / TILE_ROWS)   // 512 tiles
#define KC 64
#define NCH (D / KC)                  // 64 chunks
#define ADS 18                        // ad row stride (u64)
#define AD_STAGE (32 * ADS)           // 32 k-pairs per stage
#define GRID 148

// smem layout (bytes)
#define XS_STAGE_B 8192               // 32 rows x 64 f32
#define OFF_AD   32768                // 4 x AD_STAGE x 8 = 18432
#define OFF_REDF 51200                // 8 x 32 x 17 x 4 = 17408
#define OFF_TS   68608                // 2 x 512 x 4 = 4096
#define SMEM_TOTAL 72704

typedef unsigned long long u64;

__device__ __forceinline__ u64 fma2(u64 a, u64 b, u64 c) {
    u64 d; asm("fma.rn.f32x2 %0,%1,%2,%3;" : "=l"(d) : "l"(a), "l"(b), "l"(c)); return d;
}
__device__ __forceinline__ u64 pack2(float lo, float hi) {
    u64 d; asm("mov.b64 %0,{%1,%2};" : "=l"(d) : "f"(lo), "f"(hi)); return d;
}
__device__ __forceinline__ float hsum2(u64 v) {
    float lo, hi; asm("mov.b64 {%0,%1},%2;" : "=f"(lo), "=f"(hi) : "l"(v)); return lo + hi;
}
__device__ __forceinline__ void cp16(uint32_t d, const void* s) {
    asm volatile("cp.async.cg.shared.global [%0],[%1],16;" :: "r"(d), "l"(s));
}
__device__ __forceinline__ void cpcommit() { asm volatile("cp.async.commit_group;"); }
__device__ __forceinline__ void cpwait2()  { asm volatile("cp.async.wait_group 2;"); }
#define BAR_SYNC(id, cnt)   asm volatile("bar.sync %0, %1;"   :: "r"(id), "r"(cnt) : "memory")
#define BAR_ARRIVE(id, cnt) asm volatile("bar.arrive %0, %1;" :: "r"(id), "r"(cnt) : "memory")
// barrier ids: 1 = producer-internal (256); FULL[buf] = 2+buf (512); EMPTY[buf] = 4+buf (512)

__global__ void __launch_bounds__(512, 1)
lora_fused_ws(const float* __restrict__ x, const float* __restrict__ A,
              const float* __restrict__ B, float* __restrict__ out)
{
    extern __shared__ __align__(16) unsigned char sm[];
    float* xs   = (float*)sm;                 // [4][32 rows][64 k]
    u64*   ad   = (u64*)(sm + OFF_AD);        // [4][32 kp][ADS]
    float* redf = (float*)(sm + OFF_REDF);    // [8][32][17]
    float* ts   = (float*)(sm + OFF_TS);      // [2][32][16]

    const int tid = threadIdx.x;
    const int bid = blockIdx.x;

    if (tid < 256) {
        // ============================ PRODUCER ============================
        const int ptid = tid;
        const int w = ptid >> 5, lane = ptid & 31;

        // x loader: row = ptid>>3 (0..31), ls = ptid&7 -> k = ls*8..ls*8+7
        const int lrow = ptid >> 3, ls = ptid & 7;
        const int lswz = (lrow + (lrow >> 4)) & 15;
        const uint32_t xs_sh = (uint32_t)__cvta_generic_to_shared(sm);
        const uint32_t xd0 = xs_sh + (uint32_t)(lrow * 256 + (((2 * ls)     ^ lswz) << 4));
        const uint32_t xd1 = xs_sh + (uint32_t)(lrow * 256 + (((2 * ls + 1) ^ lswz) << 4));

        // A loader: ar = ptid>>4, a16 = ptid&15 -> k-pairs 2*a16, 2*a16+1
        const int ar = ptid >> 4, a16 = ptid & 15;
        const float* asrc = A + (long)ar * D + a16 * 4;

        // compute: lane = row; warp w owns k = 8w..8w+7 (kp 4w..4w+3)
        const int swz = (lane + (lane >> 4)) & 15;
        const int s0off = (((2 * w)     ^ swz) << 2);   // float offsets
        const int s1off = (((2 * w + 1) ^ swz) << 2);
        const float* xrow = xs + lane * 64;

        int j = 0;
        for (int tile = bid; tile < NT; tile += GRID, ++j) {
            const int buf = j & 1;
            if (j >= 2) BAR_SYNC(4 + buf, 512);   // ts[buf] free (consumers done)

            const long rowBase = (long)tile * TILE_ROWS;
            const float* xsrc = x + (rowBase + lrow) * D + ls * 8;

            u64 acc[16];
            #pragma unroll
            for (int r = 0; r < 16; ++r) acc[r] = 0ULL;

            // prologue: x(0..2) in flight, A(0..1) staged, A(2) in regs
            #pragma unroll
            for (int cc = 0; cc < 3; ++cc) {
                cp16(xd0 + (uint32_t)(cc * XS_STAGE_B), xsrc + cc * KC);
                cp16(xd1 + (uint32_t)(cc * XS_STAGE_B), xsrc + cc * KC + 4);
                cpcommit();
            }
            {
                float4 t0 = *(const float4*)(asrc);
                float4 t1 = *(const float4*)(asrc + KC);
                ad[0 * AD_STAGE + (2 * a16) * ADS + ar]     = pack2(t0.x, t0.y);
                ad[0 * AD_STAGE + (2 * a16 + 1) * ADS + ar] = pack2(t0.z, t0.w);
                ad[1 * AD_STAGE + (2 * a16) * ADS + ar]     = pack2(t1.x, t1.y);
                ad[1 * AD_STAGE + (2 * a16 + 1) * ADS + ar] = pack2(t1.z, t1.w);
            }
            float4 apf = *(const float4*)(asrc + 2 * KC);

            for (int c = 0; c < NCH; ++c) {
                const int s = c & 3;
                cpwait2();               // x(c) landed (this thread's groups)
                BAR_SYNC(1, 256);        // producer-wide visibility + WAR

                if (c + 3 < NCH) {
                    cp16(xd0 + (uint32_t)(((c + 3) & 3) * XS_STAGE_B), xsrc + (c + 3) * KC);
                    cp16(xd1 + (uint32_t)(((c + 3) & 3) * XS_STAGE_B), xsrc + (c + 3) * KC + 4);
                }
                cpcommit();              // always: group count tracks chunks

                if (c + 2 < NCH) {
                    u64* adn = ad + ((c + 2) & 3) * AD_STAGE;
                    adn[(2 * a16) * ADS + ar]     = pack2(apf.x, apf.y);
                    adn[(2 * a16 + 1) * ADS + ar] = pack2(apf.z, apf.w);
                }
                if (c + 3 < NCH)
                    apf = *(const float4*)(asrc + (c + 3) * KC);

                // compute chunk c
                const float* xb = xrow + s * 2048;
                ulonglong2 xa = *(const ulonglong2*)(xb + s0off);  // kp 4w, 4w+1
                ulonglong2 xc = *(const ulonglong2*)(xb + s1off);  // kp 4w+2, 4w+3
                u64 xk[4] = { xa.x, xa.y, xc.x, xc.y };
                const u64* adc = ad + s * AD_STAGE;
                #pragma unroll
                for (int kp2 = 0; kp2 < 4; ++kp2) {
                    const u64 xv = xk[kp2];
                    const u64* adk = adc + (4 * w + kp2) * ADS;
                    #pragma unroll
                    for (int rr = 0; rr < 8; ++rr) {
                        ulonglong2 av = *(const ulonglong2*)(adk + 2 * rr); // broadcast
                        acc[2 * rr]     = fma2(xv, av.x, acc[2 * rr]);
                        acc[2 * rr + 1] = fma2(xv, av.y, acc[2 * rr + 1]);
                    }
                }
            }

            // cross-warp k-reduction into ts[buf]
            #pragma unroll
            for (int r = 0; r < 16; ++r)
                redf[w * 544 + lane * 17 + r] = hsum2(acc[r]);
            BAR_SYNC(1, 256);
            {
                const int e = 2 * ptid;          // 0..510
                const int row = e >> 4, r = e & 15;
                float s0 = 0.f, s1 = 0.f;
                #pragma unroll
                for (int ww = 0; ww < 8; ++ww) {
                    s0 += redf[ww * 544 + row * 17 + r];
                    s1 += redf[ww * 544 + row * 17 + r + 1];
                }
                *(float2*)(ts + buf * 512 + row * 16 + r) = make_float2(s0, s1);
            }
            BAR_ARRIVE(2 + buf, 512);            // publish ts[buf]
        }
    } else {
        // ============================ CONSUMER ============================
        const int ctid = tid - 256;
        int j = 0;
        for (int tile = bid; tile < NT; tile += GRID, ++j) {
            const int buf = j & 1;
            BAR_SYNC(2 + buf, 512);              // wait ts[buf] full
            const long rowBase = (long)tile * TILE_ROWS;
            const float* tsb = ts + buf * 512;

            #pragma unroll 1
            for (int strip = 0; strip < 4; ++strip) {
                const int ob = strip * 1024 + ctid * 4;
                u64 bb[4][8];
                #pragma unroll
                for (int jj = 0; jj < 4; ++jj) {
                    const float* bp = B + (long)(ob + jj) * R;
                    ulonglong2 v0 = *(const ulonglong2*)(bp);
                    ulonglong2 v1 = *(const ulonglong2*)(bp + 4);
                    ulonglong2 v2 = *(const ulonglong2*)(bp + 8);
                    ulonglong2 v3 = *(const ulonglong2*)(bp + 12);
                    bb[jj][0] = v0.x; bb[jj][1] = v0.y;
                    bb[jj][2] = v1.x; bb[jj][3] = v1.y;
                    bb[jj][4] = v2.x; bb[jj][5] = v2.y;
                    bb[jj][6] = v3.x; bb[jj][7] = v3.y;
                }
                for (int row = 0; row < TILE_ROWS; ++row) {
                    u64 tt[8];
                    #pragma unroll
                    for (int q = 0; q < 4; ++q) {
                        ulonglong2 v = *(const ulonglong2*)(tsb + row * 16 + q * 4);
                        tt[2 * q]     = v.x;
                        tt[2 * q + 1] = v.y;
                    }
                    float res[4];
                    #pragma unroll
                    for (int jj = 0; jj < 4; ++jj) {
                        u64 a = 0ULL;
                        #pragma unroll
                        for (int p = 0; p < 8; ++p)
                            a = fma2(bb[jj][p], tt[p], a);
                        res[jj] = hsum2(a);
                    }
                    *(float4*)(out + (rowBase + row) * (long)D + ob) =
                        make_float4(res[0], res[1], res[2], res[3]);
                }
            }
            BAR_ARRIVE(4 + buf, 512);            // ts[buf] empty
        }
    }
}

extern "C" void kernel_launch(void* const* d_in, const int* in_sizes, int n_in,
                              void* d_out, int out_size) {
    const float* x = (const float*)d_in[0];   // [16384, 4096]
    const float* A = (const float*)d_in[1];   // [16, 4096]
    const float* B = (const float*)d_in[2];   // [4096, 16]
    float* out = (float*)d_out;               // [16384, 4096]

    cudaFuncSetAttribute(lora_fused_ws,
                         cudaFuncAttributeMaxDynamicSharedMemorySize, SMEM_TOTAL);
    lora_fused_ws<<<GRID, 512, SMEM_TOTAL>>>(x, A, B, out);
}

// round 17
// speedup vs baseline: 1.2498x; 1.2498x over previous
#include <cuda_runtime.h>
#include <cstdint>

// LoRA linear via rank-16 factor:
//   t   = x @ A^T   : [16384,4096] @ [4096,16] -> [16384,16]   (stage 1)
//   out = t @ B^T   : [16384,16]   @ [16,4096] -> [16384,4096] (stage 2)

#define D 4096
#define R 16
#define ROWS_TOTAL 16384
#define KC 64
#define NCH (D / KC)          // 64 chunks
#define ADS 18                // ad row stride (u64)
#define AD_STAGE (32 * ADS)   // 32 k-pairs per stage
#define XS_STAGE_B 8192       // 32 rows x 64 f32
#define OFF_AD (4 * XS_STAGE_B)              // 32768
#define S1_SMEM (OFF_AD + 4 * AD_STAGE * 8)  // 32768 + 18432 = 51200

typedef unsigned long long u64;

__device__ float g_t[ROWS_TOTAL * R];   // 1 MB scratch (fully overwritten)

__device__ __forceinline__ u64 fma2(u64 a, u64 b, u64 c) {
    u64 d; asm("fma.rn.f32x2 %0,%1,%2,%3;" : "=l"(d) : "l"(a), "l"(b), "l"(c)); return d;
}
__device__ __forceinline__ u64 pack2(float lo, float hi) {
    u64 d; asm("mov.b64 %0,{%1,%2};" : "=l"(d) : "f"(lo), "f"(hi)); return d;
}
__device__ __forceinline__ float hsum2(u64 v) {
    float lo, hi; asm("mov.b64 {%0,%1},%2;" : "=f"(lo), "=f"(hi) : "l"(v)); return lo + hi;
}
__device__ __forceinline__ void cp16(uint32_t d, const void* s) {
    asm volatile("cp.async.cg.shared.global [%0],[%1],16;" :: "r"(d), "l"(s));
}
__device__ __forceinline__ void cpcommit() { asm volatile("cp.async.commit_group;"); }
__device__ __forceinline__ void cpwait2()  { asm volatile("cp.async.wait_group 2;"); }

// ---------------- Stage 1: t = x @ A^T ----------------
// Block 256 thr / 8 warps, 32 rows, grid 512, 2 CTAs/SM (full 128-reg budget:
// acc is only 16 u64, leaving room to hoist the A-broadcast LDS batch).
// Lane = row; warp w owns k = 8w..8w+7 (k-pairs 4w..4w+3); f32x2 over
// (k-even,k-odd). Broadcast-A ad table; 4-stage cp.async ring; ONE
// __syncthreads per chunk; wait_group 2 (3 chunks in flight).
__global__ void __launch_bounds__(256, 2)
lora_stage1(const float* __restrict__ x, const float* __restrict__ A)
{
    extern __shared__ __align__(16) unsigned char sm[];
    float* xs   = (float*)sm;                 // [4][32 rows][64 k]
    u64*   ad   = (u64*)(sm + OFF_AD);        // [4][32 kp][ADS]
    float* redf = (float*)sm;                 // [8][32][17] overlay (17408 B)

    const int tid  = threadIdx.x;
    const int w    = tid >> 5;
    const int lane = tid & 31;
    const long rowBase = (long)blockIdx.x * 32;

    // x loader: row = tid>>3 (0..31), ls = tid&7 -> 16B slots 2ls, 2ls+1
    const int lrow = tid >> 3, ls = tid & 7;
    const int lswz = (lrow + (lrow >> 4)) & 15;
    const uint32_t xs_sh = (uint32_t)__cvta_generic_to_shared(sm);
    const uint32_t xd0 = xs_sh + (uint32_t)(lrow * 256 + (((2 * ls)     ^ lswz) << 4));
    const uint32_t xd1 = xs_sh + (uint32_t)(lrow * 256 + (((2 * ls + 1) ^ lswz) << 4));
    const float* xsrc = x + (rowBase + lrow) * D + ls * 8;

    // A loader: ar = tid>>4 (0..15), a16 = tid&15 -> k-pairs 2*a16, 2*a16+1
    const int ar = tid >> 4, a16 = tid & 15;
    const float* asrc = A + (long)ar * D + a16 * 4;

    // compute: lane = row; warp w reads 16B slots (2w)^swz, (2w+1)^swz
    const int swz = (lane + (lane >> 4)) & 15;
    const int s0off = (((2 * w)     ^ swz) << 2);
    const int s1off = (((2 * w + 1) ^ swz) << 2);
    const float* xrow = xs + lane * 64;

    u64 acc[16];
    #pragma unroll
    for (int r = 0; r < 16; ++r) acc[r] = 0ULL;

    // ---- prologue: x(0..2) in flight, A(0..1) staged, A(2) in regs ----
    #pragma unroll
    for (int cc = 0; cc < 3; ++cc) {
        cp16(xd0 + (uint32_t)(cc * XS_STAGE_B), xsrc + cc * KC);
        cp16(xd1 + (uint32_t)(cc * XS_STAGE_B), xsrc + cc * KC + 4);
        cpcommit();
    }
    {
        float4 t0 = *(const float4*)(asrc);
        float4 t1 = *(const float4*)(asrc + KC);
        ad[0 * AD_STAGE + (2 * a16) * ADS + ar]     = pack2(t0.x, t0.y);
        ad[0 * AD_STAGE + (2 * a16 + 1) * ADS + ar] = pack2(t0.z, t0.w);
        ad[1 * AD_STAGE + (2 * a16) * ADS + ar]     = pack2(t1.x, t1.y);
        ad[1 * AD_STAGE + (2 * a16 + 1) * ADS + ar] = pack2(t1.z, t1.w);
    }
    float4 apf = *(const float4*)(asrc + 2 * KC);

    for (int c = 0; c < NCH; ++c) {
        const int s = c & 3;
        cpwait2();           // x(c) landed (this thread's groups)
        __syncthreads();     // visible block-wide + compute(c-1) done

        if (c + 3 < NCH) {
            cp16(xd0 + (uint32_t)(((c + 3) & 3) * XS_STAGE_B), xsrc + (c + 3) * KC);
            cp16(xd1 + (uint32_t)(((c + 3) & 3) * XS_STAGE_B), xsrc + (c + 3) * KC + 4);
        }
        cpcommit();          // always: group count tracks chunk count

        if (c + 2 < NCH) {
            u64* adn = ad + ((c + 2) & 3) * AD_STAGE;
            adn[(2 * a16) * ADS + ar]     = pack2(apf.x, apf.y);
            adn[(2 * a16 + 1) * ADS + ar] = pack2(apf.z, apf.w);
        }
        if (c + 3 < NCH)
            apf = *(const float4*)(asrc + (c + 3) * KC);

        // ---- compute chunk c: k-pairs 4w..4w+3 ----
        const float* xb = xrow + s * 2048;
        ulonglong2 xa = *(const ulonglong2*)(xb + s0off);  // kp 4w, 4w+1
        ulonglong2 xc = *(const ulonglong2*)(xb + s1off);  // kp 4w+2, 4w+3
        u64 xk[4] = { xa.x, xa.y, xc.x, xc.y };
        const u64* adc = ad + s * AD_STAGE;
        #pragma unroll
        for (int kp2 = 0; kp2 < 4; ++kp2) {
            const u64 xv = xk[kp2];
            const u64* adk = adc + (4 * w + kp2) * ADS;
            #pragma unroll
            for (int rr = 0; rr < 8; ++rr) {
                ulonglong2 av = *(const ulonglong2*)(adk + 2 * rr);  // broadcast
                acc[2 * rr]     = fma2(xv, av.x, acc[2 * rr]);
                acc[2 * rr + 1] = fma2(xv, av.y, acc[2 * rr + 1]);
            }
        }
    }

    // ---- cross-warp k-reduction -> g_t ----
    __syncthreads();   // done with xs/ad -> overlay redf
    #pragma unroll
    for (int r = 0; r < 16; ++r)
        redf[w * 544 + lane * 17 + r] = hsum2(acc[r]);
    __syncthreads();
    {
        const int e = 2 * tid;           // 0..510
        const int row = e >> 4, r = e & 15;
        float s0 = 0.f, s1 = 0.f;
        #pragma unroll
        for (int ww = 0; ww < 8; ++ww) {
            s0 += redf[ww * 544 + row * 17 + r];
            s1 += redf[ww * 544 + row * 17 + r + 1];
        }
        *(float2*)(g_t + (rowBase + row) * R + r) = make_float2(s0, s1);
    }
}

// ---------------- Stage 2: out = t @ B^T ----------------
// R6 body, 2 cols/thread (bb = 32 regs) -> 3 CTAs/SM for latency hiding.
// Block 256 thr, tile 128 rows x 512 cols, grid (8, 128).
__global__ void __launch_bounds__(256, 3)
lora_stage2(const float* __restrict__ B, float* __restrict__ out)
{
    __shared__ float ts[128 * R];   // 8 KB

    const int tid = threadIdx.x;
    const long rowBase = (long)blockIdx.y * 128;
    const int ob = blockIdx.x * 512 + tid * 2;

    *(float4*)(ts + tid * 8)     = *(const float4*)(g_t + rowBase * R + tid * 8);
    *(float4*)(ts + tid * 8 + 4) = *(const float4*)(g_t + rowBase * R + tid * 8 + 4);

    u64 bb[2][8];
    #pragma unroll
    for (int j = 0; j < 2; ++j) {
        const float* bp = B + (long)(ob + j) * R;
        ulonglong2 v0 = *(const ulonglong2*)(bp);
        ulonglong2 v1 = *(const ulonglong2*)(bp + 4);
        ulonglong2 v2 = *(const ulonglong2*)(bp + 8);
        ulonglong2 v3 = *(const ulonglong2*)(bp + 12);
        bb[j][0] = v0.x; bb[j][1] = v0.y;
        bb[j][2] = v1.x; bb[j][3] = v1.y;
        bb[j][4] = v2.x; bb[j][5] = v2.y;
        bb[j][6] = v3.x; bb[j][7] = v3.y;
    }
    __syncthreads();

    #pragma unroll 2
    for (int row = 0; row < 128; ++row) {
        u64 tt[8];
        #pragma unroll
        for (int q = 0; q < 4; ++q) {
            ulonglong2 v = *(const ulonglong2*)(ts + row * R + q * 4);
            tt[2 * q]     = v.x;
            tt[2 * q + 1] = v.y;
        }
        u64 a0 = 0ULL, a1 = 0ULL;
        #pragma unroll
        for (int p = 0; p < 8; ++p) {
            a0 = fma2(bb[0][p], tt[p], a0);
            a1 = fma2(bb[1][p], tt[p], a1);
        }
        *(float2*)(out + (rowBase + row) * (long)D + ob) =
            make_float2(hsum2(a0), hsum2(a1));
    }
}

extern "C" void kernel_launch(void* const* d_in, const int* in_sizes, int n_in,
                              void* d_out, int out_size) {
    const float* x = (const float*)d_in[0];   // [16384, 4096]
    const float* A = (const float*)d_in[1];   // [16, 4096]
    const float* B = (const float*)d_in[2];   // [4096, 16]
    float* out = (float*)d_out;               // [16384, 4096]

    cudaFuncSetAttribute(lora_stage1,
                         cudaFuncAttributeMaxDynamicSharedMemorySize, S1_SMEM);
    lora_stage1<<<ROWS_TOTAL / 32, 256, S1_SMEM>>>(x, A);
    dim3 g2(D / 512, ROWS_TOTAL / 128);
    lora_stage2<<<g2, 256>>>(B, out);
}